// round 4
// baseline (speedup 1.0000x reference)
#include <cuda_runtime.h>
#include <cstdint>

// Problem constants (fixed by the dataset)
#define DHN 512
#define BN  64
#define TN  1024
#define CLUSTER 8
#define HPC 64        // h rows per CTA
#define BPC 4         // batches per cluster
#define RPAD 68       // padded 64-float group (bank-conflict-free across dg)
#define RSTRIDE (8*RPAD)  // 544 floats per (buf, batch) row

__device__ __forceinline__ float sigmoidf_(float x){ return 1.0f/(1.0f + __expf(-x)); }

__device__ __forceinline__ unsigned long long pack2(float lo, float hi){
    unsigned long long r; asm("mov.b64 %0, {%1,%2};" : "=l"(r) : "f"(lo), "f"(hi)); return r;
}
__device__ __forceinline__ void unpack2(unsigned long long v, float &lo, float &hi){
    asm("mov.b64 {%0,%1}, %2;" : "=f"(lo), "=f"(hi) : "l"(v));
}
__device__ __forceinline__ void fma2(unsigned long long &acc, unsigned long long a, unsigned long long b){
    asm("fma.rn.f32x2 %0, %1, %2, %3;" : "=l"(acc) : "l"(a), "l"(b), "l"(acc));
}
__device__ __forceinline__ uint32_t smem_u32(const void* p){
    uint32_t a; asm("{ .reg .u64 t; cvta.to.shared.u64 t, %1; cvt.u32.u64 %0, t; }" : "=r"(a) : "l"(p)); return a;
}
__device__ __forceinline__ uint32_t mapa_(uint32_t addr, uint32_t rank){
    uint32_t r; asm("mapa.shared::cluster.u32 %0, %1, %2;" : "=r"(r) : "r"(addr), "r"(rank)); return r;
}
__device__ __forceinline__ void st_cluster_f32(uint32_t addr, float v){
    asm volatile("st.shared::cluster.f32 [%0], %1;" :: "r"(addr), "f"(v) : "memory");
}
__device__ __forceinline__ void cluster_sync_(){
    asm volatile("barrier.cluster.arrive.aligned;" ::: "memory");
    asm volatile("barrier.cluster.wait.aligned;" ::: "memory");
}
__device__ __forceinline__ uint32_t ctarank_(){
    uint32_t r; asm("mov.u32 %0, %%cluster_ctarank;" : "=r"(r)); return r;
}

// Main recurrent kernel: 16 clusters x 8 CTAs x 512 threads.
// CTA = (cluster c, rank p). Owns h rows [p*64, p*64+64) for batches [4c, 4c+4).
// Thread tid = h_local*8 + dg; owns W[hg, dg*64 : dg*64+64) in 32 f32x2 registers.
__global__ void __cluster_dims__(CLUSTER,1,1) __launch_bounds__(512,1)
rnn_main(const float* __restrict__ u, const float* __restrict__ r0,
         const float* __restrict__ noise, const float* __restrict__ win,
         const float* __restrict__ m, const float* __restrict__ w_raw,
         const float* __restrict__ taus, float* __restrict__ xs)
{
    __shared__ __align__(16) float r_sh[2][BPC][RSTRIDE];   // double-buffered r vectors

    const int tid = threadIdx.x;
    const int h_local = tid >> 3;
    const int dg = tid & 7;
    const uint32_t rank = ctarank_();
    const int cid = blockIdx.x / CLUSTER;
    const int hg = (int)rank * HPC + h_local;
    const int bbase = cid * BPC;

    // --- Load W slice into registers: w = |_w[h,d] * m[d,d]|, packed f32x2 over d ---
    unsigned long long w2[32];
    {
        const float* wr = w_raw + (size_t)hg * DHN + dg*64;
        #pragma unroll
        for (int k = 0; k < 32; k++){
            int d0 = dg*64 + 2*k;
            float a = fabsf(wr[2*k]   * m[(size_t)d0*DHN + d0]);
            float b = fabsf(wr[2*k+1] * m[(size_t)(d0+1)*DHN + (d0+1)]);
            w2[k] = pack2(a, b);
        }
    }

    const float a_h   = 1.0f / taus[hg];
    const float win_h = win[hg];

    // Epilogue lane (dg<4) owns batch b = dg for row hg.
    const int b  = dg & 3;
    const int bg = bbase + b;
    float s_reg = 0.0f;                 // carried x_in for (bg, hg)

    // Precompute DSMEM broadcast targets for this lane's r slot, both buffers.
    uint32_t dst[2][8];
    {
        uint32_t base0 = smem_u32(&r_sh[0][b][(int)rank*RPAD + h_local]);
        uint32_t base1 = smem_u32(&r_sh[1][b][(int)rank*RPAD + h_local]);
        #pragma unroll
        for (int p = 0; p < 8; p++){
            dst[0][p] = mapa_(base0, (uint32_t)p);
            dst[1][p] = mapa_(base1, (uint32_t)p);
        }
    }

    // --- Prologue: s0 = r0; broadcast r_0 = sigmoid(s0) into buffer 0 ---
    if (dg < 4){
        s_reg = r0[(size_t)bg*DHN + hg];
        float rv = sigmoidf_(s_reg);
        #pragma unroll
        for (int p = 0; p < 8; p++) st_cluster_f32(dst[0][p], rv);
    }
    cluster_sync_();

    for (int t = 0; t < TN; t++){
        const int buf = t & 1;

        // Prefetch this step's noise/input early (hide DRAM latency behind matvec)
        float noise_v = 0.0f, u_v = 0.0f;
        if (dg < 4){
            noise_v = noise[((size_t)t*BN + bg)*DHN + hg];
            u_v     = u[(size_t)bg*TN + t];
        }

        // Partial dot products: sum_{d in dg slice} W[hg,d] * r[b,d], all 4 batches
        float sum[BPC];
        #pragma unroll
        for (int bb = 0; bb < BPC; bb++){
            const ulonglong2* rp = (const ulonglong2*)&r_sh[buf][bb][dg*RPAD];
            unsigned long long a0 = 0ull, a1 = 0ull;
            #pragma unroll
            for (int k = 0; k < 16; k++){
                ulonglong2 rv = rp[k];
                fma2(a0, w2[2*k],   rv.x);
                fma2(a1, w2[2*k+1], rv.y);
            }
            float l0,h0,l1,h1; unpack2(a0,l0,h0); unpack2(a1,l1,h1);
            sum[bb] = (l0+h0)+(l1+h1);
        }

        // Reduce across the 8 dg lanes (lane bits 0..2) — butterfly, all lanes get totals
        #pragma unroll
        for (int bb = 0; bb < BPC; bb++){
            sum[bb] += __shfl_xor_sync(0xffffffffu, sum[bb], 1);
            sum[bb] += __shfl_xor_sync(0xffffffffu, sum[bb], 2);
            sum[bb] += __shfl_xor_sync(0xffffffffu, sum[bb], 4);
        }

        if (dg < 4){
            float dot = sum[b];
            float xn  = (1.0f - a_h)*s_reg + a_h*dot + win_h*u_v + 0.1f*noise_v;
            xs[((size_t)bg*DHN + hg)*TN + t] = xn;      // xs output (B, DH, T)
            s_reg = sigmoidf_(xn);                       // next x_in
            float rv = sigmoidf_(s_reg);                 // next r
            const int nb = buf ^ 1;
            #pragma unroll
            for (int p = 0; p < 8; p++) st_cluster_f32(dst[nb][p], rv);
        }
        cluster_sync_();
    }
}

// Post-pass: outputs[b,t] = sum_h wout[h] * sigmoid(xs[b,h,t]) + bias
__global__ void __launch_bounds__(256)
rnn_out(const float* __restrict__ xs, const float* __restrict__ wout,
        const float* __restrict__ bias, float* __restrict__ out)
{
    __shared__ float wsh[DHN];
    const int bb = blockIdx.x;
    for (int i = threadIdx.x; i < DHN; i += 256) wsh[i] = wout[i];
    __syncthreads();

    float acc0=0.f, acc1=0.f, acc2=0.f, acc3=0.f;
    const float4* base = (const float4*)(xs + (size_t)bb*DHN*TN);
    #pragma unroll 1
    for (int h = 0; h < DHN; h++){
        float wv = wsh[h];
        float4 v = base[(size_t)h*(TN/4) + threadIdx.x];
        acc0 = fmaf(wv, sigmoidf_(v.x), acc0);
        acc1 = fmaf(wv, sigmoidf_(v.y), acc1);
        acc2 = fmaf(wv, sigmoidf_(v.z), acc2);
        acc3 = fmaf(wv, sigmoidf_(v.w), acc3);
    }
    float bz = bias[0];
    float4 o; o.x = acc0+bz; o.y = acc1+bz; o.z = acc2+bz; o.w = acc3+bz;
    ((float4*)(out + (size_t)bb*TN))[threadIdx.x] = o;
}

extern "C" void kernel_launch(void* const* d_in, const int* in_sizes, int n_in,
                              void* d_out, int out_size)
{
    // metadata order: u, r0, noise, win, m, wout, _w, taus, bias
    const float* u     = (const float*)d_in[0];
    const float* r0    = (const float*)d_in[1];
    const float* noise = (const float*)d_in[2];
    const float* win   = (const float*)d_in[3];
    const float* m     = (const float*)d_in[4];
    const float* wout  = (const float*)d_in[5];
    const float* w_raw = (const float*)d_in[6];
    const float* taus  = (const float*)d_in[7];
    const float* bias  = (const float*)d_in[8];

    float* out = (float*)d_out;                    // outputs (B, T, 1) first
    float* xs  = out + (size_t)BN * TN;            // then xs (B, DH, T)

    rnn_main<<<16*CLUSTER, 512>>>(u, r0, noise, win, m, w_raw, taus, xs);
    rnn_out<<<BN, 256>>>(xs, wout, bias, out);
}

// round 5
// speedup vs baseline: 1.0002x; 1.0002x over previous
#include <cuda_runtime.h>
#include <cstdint>

// Problem constants (fixed by the dataset)
#define DHN 512
#define BN  64
#define TN  1024
#define CLUSTER 8
#define HPC 64        // h rows per CTA
#define BPC 4         // batches per cluster
#define RPAD 68       // padded 64-float group (bank-conflict-free across dg)
#define RSTRIDE (8*RPAD)  // 544 floats per (buf, batch) row

__device__ __forceinline__ float sigmoidf_(float x){ return 1.0f/(1.0f + __expf(-x)); }

__device__ __forceinline__ unsigned long long pack2(float lo, float hi){
    unsigned long long r; asm("mov.b64 %0, {%1,%2};" : "=l"(r) : "f"(lo), "f"(hi)); return r;
}
__device__ __forceinline__ void unpack2(unsigned long long v, float &lo, float &hi){
    asm("mov.b64 {%0,%1}, %2;" : "=f"(lo), "=f"(hi) : "l"(v));
}
__device__ __forceinline__ void fma2(unsigned long long &acc, unsigned long long a, unsigned long long b){
    asm("fma.rn.f32x2 %0, %1, %2, %3;" : "=l"(acc) : "l"(a), "l"(b), "l"(acc));
}
__device__ __forceinline__ uint32_t smem_u32(const void* p){
    uint32_t a; asm("{ .reg .u64 t; cvta.to.shared.u64 t, %1; cvt.u32.u64 %0, t; }" : "=r"(a) : "l"(p)); return a;
}
__device__ __forceinline__ uint32_t mapa_(uint32_t addr, uint32_t rank){
    uint32_t r; asm("mapa.shared::cluster.u32 %0, %1, %2;" : "=r"(r) : "r"(addr), "r"(rank)); return r;
}
__device__ __forceinline__ void st_cluster_f32(uint32_t addr, float v){
    asm volatile("st.shared::cluster.f32 [%0], %1;" :: "r"(addr), "f"(v) : "memory");
}
__device__ __forceinline__ void cluster_sync_(){
    asm volatile("barrier.cluster.arrive.aligned;" ::: "memory");
    asm volatile("barrier.cluster.wait.aligned;" ::: "memory");
}
__device__ __forceinline__ uint32_t ctarank_(){
    uint32_t r; asm("mov.u32 %0, %%cluster_ctarank;" : "=r"(r)); return r;
}

// Main recurrent kernel: 16 clusters x 8 CTAs x 512 threads.
// CTA = (cluster c, rank p). Owns h rows [p*64, p*64+64) for batches [4c, 4c+4).
// Thread tid = h_local*8 + dg; owns W[hg, dg*64 : dg*64+64) in 32 f32x2 registers.
__global__ void __cluster_dims__(CLUSTER,1,1) __launch_bounds__(512,1)
rnn_main(const float* __restrict__ u, const float* __restrict__ r0,
         const float* __restrict__ noise, const float* __restrict__ win,
         const float* __restrict__ m, const float* __restrict__ w_raw,
         const float* __restrict__ taus, float* __restrict__ xs)
{
    __shared__ __align__(16) float r_sh[2][BPC][RSTRIDE];   // double-buffered r vectors

    const int tid = threadIdx.x;
    const int h_local = tid >> 3;
    const int dg = tid & 7;
    const uint32_t rank = ctarank_();
    const int cid = blockIdx.x / CLUSTER;
    const int hg = (int)rank * HPC + h_local;
    const int bbase = cid * BPC;

    // --- Load W slice into registers: w = |_w[h,d] * m[d,d]|, packed f32x2 over d ---
    unsigned long long w2[32];
    {
        const float* wr = w_raw + (size_t)hg * DHN + dg*64;
        #pragma unroll
        for (int k = 0; k < 32; k++){
            int d0 = dg*64 + 2*k;
            float a = fabsf(wr[2*k]   * m[(size_t)d0*DHN + d0]);
            float b = fabsf(wr[2*k+1] * m[(size_t)(d0+1)*DHN + (d0+1)]);
            w2[k] = pack2(a, b);
        }
    }

    const float a_h   = 1.0f / taus[hg];
    const float win_h = win[hg];

    // Epilogue lane (dg<4) owns batch b = dg for row hg.
    const int b  = dg & 3;
    const int bg = bbase + b;
    float s_reg = 0.0f;                 // carried x_in for (bg, hg)

    // Precompute DSMEM broadcast targets for this lane's r slot, both buffers.
    uint32_t dst[2][8];
    {
        uint32_t base0 = smem_u32(&r_sh[0][b][(int)rank*RPAD + h_local]);
        uint32_t base1 = smem_u32(&r_sh[1][b][(int)rank*RPAD + h_local]);
        #pragma unroll
        for (int p = 0; p < 8; p++){
            dst[0][p] = mapa_(base0, (uint32_t)p);
            dst[1][p] = mapa_(base1, (uint32_t)p);
        }
    }

    // --- Prologue: s0 = r0; broadcast r_0 = sigmoid(s0) into buffer 0 ---
    if (dg < 4){
        s_reg = r0[(size_t)bg*DHN + hg];
        float rv = sigmoidf_(s_reg);
        #pragma unroll
        for (int p = 0; p < 8; p++) st_cluster_f32(dst[0][p], rv);
    }
    cluster_sync_();

    for (int t = 0; t < TN; t++){
        const int buf = t & 1;

        // Prefetch this step's noise/input early (hide DRAM latency behind matvec)
        float noise_v = 0.0f, u_v = 0.0f;
        if (dg < 4){
            noise_v = noise[((size_t)t*BN + bg)*DHN + hg];
            u_v     = u[(size_t)bg*TN + t];
        }

        // Partial dot products: sum_{d in dg slice} W[hg,d] * r[b,d], all 4 batches
        float sum[BPC];
        #pragma unroll
        for (int bb = 0; bb < BPC; bb++){
            const ulonglong2* rp = (const ulonglong2*)&r_sh[buf][bb][dg*RPAD];
            unsigned long long a0 = 0ull, a1 = 0ull;
            #pragma unroll
            for (int k = 0; k < 16; k++){
                ulonglong2 rv = rp[k];
                fma2(a0, w2[2*k],   rv.x);
                fma2(a1, w2[2*k+1], rv.y);
            }
            float l0,h0,l1,h1; unpack2(a0,l0,h0); unpack2(a1,l1,h1);
            sum[bb] = (l0+h0)+(l1+h1);
        }

        // Reduce across the 8 dg lanes (lane bits 0..2) — butterfly, all lanes get totals
        #pragma unroll
        for (int bb = 0; bb < BPC; bb++){
            sum[bb] += __shfl_xor_sync(0xffffffffu, sum[bb], 1);
            sum[bb] += __shfl_xor_sync(0xffffffffu, sum[bb], 2);
            sum[bb] += __shfl_xor_sync(0xffffffffu, sum[bb], 4);
        }

        if (dg < 4){
            float dot = sum[b];
            float xn  = (1.0f - a_h)*s_reg + a_h*dot + win_h*u_v + 0.1f*noise_v;
            xs[((size_t)bg*DHN + hg)*TN + t] = xn;      // xs output (B, DH, T)
            s_reg = sigmoidf_(xn);                       // next x_in
            float rv = sigmoidf_(s_reg);                 // next r
            const int nb = buf ^ 1;
            #pragma unroll
            for (int p = 0; p < 8; p++) st_cluster_f32(dst[nb][p], rv);
        }
        cluster_sync_();
    }
}

// Post-pass: outputs[b,t] = sum_h wout[h] * sigmoid(xs[b,h,t]) + bias
__global__ void __launch_bounds__(256)
rnn_out(const float* __restrict__ xs, const float* __restrict__ wout,
        const float* __restrict__ bias, float* __restrict__ out)
{
    __shared__ float wsh[DHN];
    const int bb = blockIdx.x;
    for (int i = threadIdx.x; i < DHN; i += 256) wsh[i] = wout[i];
    __syncthreads();

    float acc0=0.f, acc1=0.f, acc2=0.f, acc3=0.f;
    const float4* base = (const float4*)(xs + (size_t)bb*DHN*TN);
    #pragma unroll 1
    for (int h = 0; h < DHN; h++){
        float wv = wsh[h];
        float4 v = base[(size_t)h*(TN/4) + threadIdx.x];
        acc0 = fmaf(wv, sigmoidf_(v.x), acc0);
        acc1 = fmaf(wv, sigmoidf_(v.y), acc1);
        acc2 = fmaf(wv, sigmoidf_(v.z), acc2);
        acc3 = fmaf(wv, sigmoidf_(v.w), acc3);
    }
    float bz = bias[0];
    float4 o; o.x = acc0+bz; o.y = acc1+bz; o.z = acc2+bz; o.w = acc3+bz;
    ((float4*)(out + (size_t)bb*TN))[threadIdx.x] = o;
}

extern "C" void kernel_launch(void* const* d_in, const int* in_sizes, int n_in,
                              void* d_out, int out_size)
{
    // metadata order: u, r0, noise, win, m, wout, _w, taus, bias
    const float* u     = (const float*)d_in[0];
    const float* r0    = (const float*)d_in[1];
    const float* noise = (const float*)d_in[2];
    const float* win   = (const float*)d_in[3];
    const float* m     = (const float*)d_in[4];
    const float* wout  = (const float*)d_in[5];
    const float* w_raw = (const float*)d_in[6];
    const float* taus  = (const float*)d_in[7];
    const float* bias  = (const float*)d_in[8];

    float* out = (float*)d_out;                    // outputs (B, T, 1) first
    float* xs  = out + (size_t)BN * TN;            // then xs (B, DH, T)

    rnn_main<<<16*CLUSTER, 512>>>(u, r0, noise, win, m, w_raw, taus, xs);
    rnn_out<<<BN, 256>>>(xs, wout, bias, out);
}

// round 6
// speedup vs baseline: 1.1401x; 1.1399x over previous
#include <cuda_runtime.h>
#include <cstdint>

#define DHN 512
#define BN  64
#define TN  1024
#define CLUSTER 8
#define HPC 64
#define BPC 4
#define RPAD 68
#define RSTRD (8*RPAD)          // 544 floats per (buf,batch) row
#define WROW 36                 // padded per-thread W smem row (32 data + 4 pad)
#define SMEM_W_FLOATS (512*WROW)            // 18432 floats = 73728 B
#define SMEM_R_FLOATS (2*BPC*RSTRD)         // 4352 floats  = 17408 B
#define SMEM_BYTES ((SMEM_W_FLOATS + SMEM_R_FLOATS)*4)

__device__ float g_sig[(size_t)BN*DHN*TN];   // sigma(x_new), reused by rnn_out
__device__ float g_part[4][BN][TN];          // deterministic partials

__device__ __forceinline__ float sigmoidf_(float x){ return 1.0f/(1.0f + __expf(-x)); }

__device__ __forceinline__ unsigned long long pack2(float lo, float hi){
    unsigned long long r; asm("mov.b64 %0, {%1,%2};" : "=l"(r) : "f"(lo), "f"(hi)); return r;
}
__device__ __forceinline__ void unpack2(unsigned long long v, float &lo, float &hi){
    asm("mov.b64 {%0,%1}, %2;" : "=f"(lo), "=f"(hi) : "l"(v));
}
__device__ __forceinline__ void fma2(unsigned long long &acc, unsigned long long a, unsigned long long b){
    asm("fma.rn.f32x2 %0, %1, %2, %3;" : "=l"(acc) : "l"(a), "l"(b), "l"(acc));
}
__device__ __forceinline__ uint32_t smem_u32(const void* p){
    uint32_t a; asm("{ .reg .u64 t; cvta.to.shared.u64 t, %1; cvt.u32.u64 %0, t; }" : "=r"(a) : "l"(p)); return a;
}
__device__ __forceinline__ uint32_t mapa_(uint32_t addr, uint32_t rank){
    uint32_t r; asm("mapa.shared::cluster.u32 %0, %1, %2;" : "=r"(r) : "r"(addr), "r"(rank)); return r;
}
__device__ __forceinline__ void st_cluster_f32(uint32_t addr, float v){
    asm volatile("st.shared::cluster.f32 [%0], %1;" :: "r"(addr), "f"(v) : "memory");
}
__device__ __forceinline__ void cluster_sync_(){
    asm volatile("barrier.cluster.arrive.aligned;" ::: "memory");
    asm volatile("barrier.cluster.wait.aligned;" ::: "memory");
}
__device__ __forceinline__ uint32_t ctarank_(){
    uint32_t r; asm("mov.u32 %0, %%cluster_ctarank;" : "=r"(r)); return r;
}

// 16 clusters x 8 CTAs x 512 threads. CTA owns 64 h-rows x 4 batches.
// Thread tid = h_local*8 + dg owns W[hg, dg*64 .. dg*64+64):
//   d-offsets 0..31  -> 16 persistent f32x2 registers
//   d-offsets 32..63 -> per-thread SMEM row (pad-36, conflict-free LDS.128)
__global__ void __cluster_dims__(CLUSTER,1,1) __launch_bounds__(512,1)
rnn_main(const float* __restrict__ u, const float* __restrict__ r0,
         const float* __restrict__ noise, const float* __restrict__ win,
         const float* __restrict__ w_raw, const float* __restrict__ taus,
         float* __restrict__ xs)
{
    extern __shared__ __align__(16) float smem[];
    float* W_sh = smem;                       // [512][36]
    float* r_sh = smem + SMEM_W_FLOATS;       // [2][4][544]

    const int tid = threadIdx.x;
    const int h_local = tid >> 3;
    const int dg = tid & 7;
    const uint32_t rank = ctarank_();
    const int cid = blockIdx.x / CLUSTER;
    const int hg = (int)rank * HPC + h_local;
    const int bbase = cid * BPC;

    // ---- Load W: |_w| (m is diag(+-1), so |_w @ m| == |_w|) ----
    unsigned long long w2p[16];
    {
        const float* wr = w_raw + (size_t)hg * DHN + dg*64;
        #pragma unroll
        for (int k = 0; k < 16; k++)
            w2p[k] = pack2(fabsf(wr[2*k]), fabsf(wr[2*k+1]));
        float* wsm = W_sh + tid*WROW;
        #pragma unroll
        for (int j = 0; j < 32; j++)
            wsm[j] = fabsf(wr[32 + j]);
    }
    const float a_h   = 1.0f / taus[hg];
    const float win_h = win[hg];

    const int b  = dg & 3;                    // epilogue lane's batch (dg<4)
    const int bg = bbase + b;
    float s_reg = 0.0f;

    // local SMEM addresses of this lane's r slot in both buffers
    const uint32_t base0 = smem_u32(&r_sh[(0*BPC + b)*RSTRD + (int)rank*RPAD + h_local]);
    const uint32_t base1 = smem_u32(&r_sh[(1*BPC + b)*RSTRD + (int)rank*RPAD + h_local]);

    // ---- Prologue ----
    if (dg < 4){
        s_reg = r0[(size_t)bg*DHN + hg];
        float rv = sigmoidf_(s_reg);
        #pragma unroll
        for (int p = 0; p < 8; p++) st_cluster_f32(mapa_(base0, (uint32_t)p), rv);
    }
    cluster_sync_();

    float* xs_ptr  = xs    + ((size_t)bg*DHN + hg)*TN;
    float* sig_ptr = g_sig + ((size_t)bg*DHN + hg)*TN;

    for (int t = 0; t < TN; t++){
        const int rbuf = (t & 1) * BPC;

        float noise_v = 0.0f, u_v = 0.0f;
        if (dg < 4){
            noise_v = noise[((size_t)t*BN + bg)*DHN + hg];
            u_v     = u[(size_t)bg*TN + t];
        }

        unsigned long long acc0[BPC], acc1[BPC];
        #pragma unroll
        for (int bb = 0; bb < BPC; bb++){ acc0[bb] = 0ull; acc1[bb] = 0ull; }

        // d-offsets 0..31 from registers
        #pragma unroll
        for (int kc = 0; kc < 4; kc++){
            #pragma unroll
            for (int bb = 0; bb < BPC; bb++){
                const ulonglong2* rp = (const ulonglong2*)(r_sh + (rbuf + bb)*RSTRD + dg*RPAD + 8*kc);
                ulonglong2 rv0 = rp[0];
                ulonglong2 rv1 = rp[1];
                fma2(acc0[bb], w2p[4*kc+0], rv0.x);
                fma2(acc1[bb], w2p[4*kc+1], rv0.y);
                fma2(acc0[bb], w2p[4*kc+2], rv1.x);
                fma2(acc1[bb], w2p[4*kc+3], rv1.y);
            }
        }
        // d-offsets 32..63 from SMEM
        {
            const ulonglong2* wp = (const ulonglong2*)(W_sh + tid*WROW);
            #pragma unroll
            for (int kc = 0; kc < 4; kc++){
                ulonglong2 wv0 = wp[2*kc];
                ulonglong2 wv1 = wp[2*kc+1];
                #pragma unroll
                for (int bb = 0; bb < BPC; bb++){
                    const ulonglong2* rp = (const ulonglong2*)(r_sh + (rbuf + bb)*RSTRD + dg*RPAD + 32 + 8*kc);
                    ulonglong2 rv0 = rp[0];
                    ulonglong2 rv1 = rp[1];
                    fma2(acc0[bb], wv0.x, rv0.x);
                    fma2(acc1[bb], wv0.y, rv0.y);
                    fma2(acc0[bb], wv1.x, rv1.x);
                    fma2(acc1[bb], wv1.y, rv1.y);
                }
            }
        }

        float sum[BPC];
        #pragma unroll
        for (int bb = 0; bb < BPC; bb++){
            float l0,h0,l1,h1; unpack2(acc0[bb],l0,h0); unpack2(acc1[bb],l1,h1);
            sum[bb] = (l0+h0)+(l1+h1);
        }
        #pragma unroll
        for (int bb = 0; bb < BPC; bb++){
            sum[bb] += __shfl_xor_sync(0xffffffffu, sum[bb], 1);
            sum[bb] += __shfl_xor_sync(0xffffffffu, sum[bb], 2);
            sum[bb] += __shfl_xor_sync(0xffffffffu, sum[bb], 4);
        }

        if (dg < 4){
            float dot = sum[b];
            float xn  = (1.0f - a_h)*s_reg + a_h*dot + win_h*u_v + 0.1f*noise_v;
            xs_ptr[t] = xn;
            s_reg = sigmoidf_(xn);            // sigma(x_new): next x_in AND rnn_out input
            sig_ptr[t] = s_reg;
            float rv = sigmoidf_(s_reg);      // next r
            const uint32_t lb = (t & 1) ? base0 : base1;
            #pragma unroll
            for (int p = 0; p < 8; p++) st_cluster_f32(mapa_(lb, (uint32_t)p), rv);
        }
        cluster_sync_();
    }
}

// Partial dot products over 128-h chunks: pure DRAM streaming, zero MUFU.
__global__ void __launch_bounds__(256)
rnn_out_part(const float* __restrict__ wout)
{
    const int b  = blockIdx.x >> 2;
    const int hc = blockIdx.x & 3;
    __shared__ float wsh[128];
    if (threadIdx.x < 128) wsh[threadIdx.x] = wout[hc*128 + threadIdx.x];
    __syncthreads();

    const float4* base = (const float4*)(g_sig + ((size_t)b*DHN + hc*128)*TN);
    float a0=0.f, a1=0.f, a2=0.f, a3=0.f;
    #pragma unroll 4
    for (int h = 0; h < 128; h++){
        float wv = wsh[h];
        float4 v = base[(size_t)h*(TN/4) + threadIdx.x];
        a0 = fmaf(wv, v.x, a0);
        a1 = fmaf(wv, v.y, a1);
        a2 = fmaf(wv, v.z, a2);
        a3 = fmaf(wv, v.w, a3);
    }
    float4 o; o.x=a0; o.y=a1; o.z=a2; o.w=a3;
    ((float4*)g_part[hc][b])[threadIdx.x] = o;
}

__global__ void __launch_bounds__(256)
rnn_combine(const float* __restrict__ bias, float* __restrict__ out)
{
    const int b = blockIdx.x;
    float4 p0 = ((const float4*)g_part[0][b])[threadIdx.x];
    float4 p1 = ((const float4*)g_part[1][b])[threadIdx.x];
    float4 p2 = ((const float4*)g_part[2][b])[threadIdx.x];
    float4 p3 = ((const float4*)g_part[3][b])[threadIdx.x];
    float bz = bias[0];
    float4 o;
    o.x = (p0.x+p1.x)+(p2.x+p3.x)+bz;
    o.y = (p0.y+p1.y)+(p2.y+p3.y)+bz;
    o.z = (p0.z+p1.z)+(p2.z+p3.z)+bz;
    o.w = (p0.w+p1.w)+(p2.w+p3.w)+bz;
    ((float4*)(out + (size_t)b*TN))[threadIdx.x] = o;
}

extern "C" void kernel_launch(void* const* d_in, const int* in_sizes, int n_in,
                              void* d_out, int out_size)
{
    // metadata order: u, r0, noise, win, m, wout, _w, taus, bias
    const float* u     = (const float*)d_in[0];
    const float* r0    = (const float*)d_in[1];
    const float* noise = (const float*)d_in[2];
    const float* win   = (const float*)d_in[3];
    const float* wout  = (const float*)d_in[5];
    const float* w_raw = (const float*)d_in[6];
    const float* taus  = (const float*)d_in[7];
    const float* bias  = (const float*)d_in[8];

    float* out = (float*)d_out;                 // outputs (B, T, 1)
    float* xs  = out + (size_t)BN * TN;         // xs (B, DH, T)

    static int smem_set = 0;
    if (!smem_set){
        cudaFuncSetAttribute(rnn_main, cudaFuncAttributeMaxDynamicSharedMemorySize, SMEM_BYTES);
        smem_set = 1;
    }

    rnn_main<<<16*CLUSTER, 512, SMEM_BYTES>>>(u, r0, noise, win, w_raw, taus, xs);
    rnn_out_part<<<BN*4, 256>>>(wout);
    rnn_combine<<<BN, 256>>>(bias, out);
}